// round 7
// baseline (speedup 1.0000x reference)
#include <cuda_runtime.h>
#include <cuda_bf16.h>
#include <cstdint>
#include <cstddef>

#define BB 16
#define IC 8
#define OC 8
#define NV 3
#define HH 256
#define WW 256
#define M1 16
#define M2 16
#define TD 256

// -------------------- static scratch (no runtime allocation) --------------------
__device__ __align__(16) float2 g_Y[BB*IC*NV*HH*16];      // fwd DFT over w
__device__ __align__(16) float2 g_X[BB*IC*NV*32*16];      // fwd modes
__device__ __align__(16) float  g_TW[4*BB*(IC*OC*NV*M1*M2)]; // time-contracted weights
__device__ __align__(16) float2 g_G[BB*OC*NV*32*16];      // mixed modes
__device__ __align__(16) float2 g_Z[BB*OC*NV*HH*16];      // inv DFT over h
// twiddle tables (computed by k0 each launch)
__device__ __align__(16) float2 g_T1[2048];               // [w][k]: e^{-2pi i k w/256}, k=0..15
__device__ __align__(16) float2 g_T2[4096];               // [h][s]: e^{-2pi i (s-16) h/256}, s=0..15
__device__ __align__(16) float  g_T5c[2048];              // [kw][w]: cos * al
__device__ __align__(16) float  g_T5s[2048];              // [kw][w]: sin * al

// ---------------------------------------------------------------------------
// k0: compute twiddle tables once per launch. 16 x 256 threads.
// ---------------------------------------------------------------------------
__global__ __launch_bounds__(256) void k0_tables() {
    const int idx = blockIdx.x * 256 + threadIdx.x;    // 0..4095
    if (idx < 2048) {
        int kw = idx >> 7, w = idx & 127;
        float sn, cs;
        sincospif((float)(kw * w) * (1.0f / 128.0f), &sn, &cs);
        float al = ((kw == 0) ? 1.0f : 2.0f) * (1.0f / 65536.0f);
        g_T5c[idx] = cs * al;
        g_T5s[idx] = sn * al;
        int w1 = idx >> 4, k = idx & 15;
        float sn1, cs1;
        sincospif((float)(k * w1) * (1.0f / 128.0f), &sn1, &cs1);
        g_T1[idx] = make_float2(cs1, -sn1);
    }
    {
        int h = idx >> 4, s = idx & 15;
        float sn, cs;
        sincospif((float)((s - 16) * h) * (1.0f / 128.0f), &sn, &cs);
        g_T2[idx] = make_float2(cs, -sn);
    }
}

// ---------------------------------------------------------------------------
// k1: forward DFT over w, modes kw=0..15. Parity split over w.
// Block: 128 threads = 16 modes x 8 row-groups; 16 rows/block. Grid: 6144.
// ---------------------------------------------------------------------------
__global__ __launch_bounds__(128) void k1_fwd_w(const float* __restrict__ x) {
    __shared__ float sx[16][256];
    __shared__ float2 stw[2048];   // [w][k]
    const int tid = threadIdx.x;

    const float4* xg = (const float4*)(x + (size_t)blockIdx.x * (16 * 256));
    float4* sx4 = (float4*)sx;
#pragma unroll
    for (int it = 0; it < 8; it++)
        sx4[it * 128 + tid] = xg[it * 128 + tid];
    float4* stw4 = (float4*)stw;
    const float4* gt4 = (const float4*)g_T1;
#pragma unroll
    for (int j = 0; j < 8; j++)
        stw4[j * 128 + tid] = gt4[j * 128 + tid];
    __syncthreads();

#pragma unroll
    for (int p = tid; p < 2048; p += 128) {
        int r = p >> 7, w = p & 127;
        float a = sx[r][w], b = sx[r][w + 128];
        sx[r][w]       = a + b;
        sx[r][w + 128] = a - b;
    }
    __syncthreads();

    const int k  = tid & 15;
    const int rg = tid >> 4;
    const int base = (k & 1) << 7;

    float ar0 = 0, ai0 = 0, ar1 = 0, ai1 = 0;
#pragma unroll 4
    for (int w4 = 0; w4 < 32; w4++) {
        float4 v0 = *(const float4*)&sx[rg    ][base + w4 * 4];
        float4 v1 = *(const float4*)&sx[rg + 8][base + w4 * 4];
        float e0[4] = {v0.x, v0.y, v0.z, v0.w};
        float e1[4] = {v1.x, v1.y, v1.z, v1.w};
#pragma unroll
        for (int u = 0; u < 4; u++) {
            float2 tw = stw[(w4 * 4 + u) * 16 + k];
            ar0 += e0[u] * tw.x; ai0 += e0[u] * tw.y;
            ar1 += e1[u] * tw.x; ai1 += e1[u] * tw.y;
        }
    }

    size_t rowbase = (size_t)blockIdx.x * 16;
    g_Y[(rowbase + rg    ) * 16 + k] = make_float2(ar0, ai0);
    g_Y[(rowbase + rg + 8) * 16 + k] = make_float2(ar1, ai1);
}

// ---------------------------------------------------------------------------
// k2: forward DFT over h for kh in {0..15} U {240..255}. One block per (b,i,v).
// 512 threads: (kw 16, s 16, hh 2); each thread sums 64 h, smem reduction.
// Grid: 384 x 512.
// ---------------------------------------------------------------------------
__global__ __launch_bounds__(512) void k2_fwd_h() {
    __shared__ float2 sy[4096];     // [h][kw]
    __shared__ float4 red[256];     // partials from hh=1
    const int tid = threadIdx.x;

    const float4* yg = (const float4*)(g_Y + (size_t)blockIdx.x * 4096);
    float4* sy4 = (float4*)sy;
#pragma unroll
    for (int it = 0; it < 4; it++)
        sy4[it * 512 + tid] = yg[it * 512 + tid];
    __syncthreads();

#pragma unroll
    for (int p = tid; p < 2048; p += 512) {
        int h = p >> 4, kw = p & 15;
        float2 a = sy[h * 16 + kw], b = sy[(h + 128) * 16 + kw];
        sy[h * 16 + kw]         = make_float2(a.x + b.x, a.y + b.y);
        sy[(h + 128) * 16 + kw] = make_float2(a.x - b.x, a.y - b.y);
    }
    __syncthreads();

    const int kw = tid & 15;
    const int s  = (tid >> 4) & 15;
    const int hh = tid >> 8;             // 0 or 1
    const int hbase = (s & 1) << 7;

    float a1r = 0, a1i = 0, a2r = 0, a2i = 0;
    const int h0 = hh * 64;
#pragma unroll 4
    for (int hi = 0; hi < 64; hi++) {
        int h = h0 + hi;
        float2 u  = sy[(hbase + h) * 16 + kw];
        float2 T1 = g_T1[h * 16 + s];
        float2 T2 = g_T2[h * 16 + s];
        a1r += u.x * T1.x - u.y * T1.y;
        a1i += u.x * T1.y + u.y * T1.x;
        a2r += u.x * T2.x - u.y * T2.y;
        a2i += u.x * T2.y + u.y * T2.x;
    }

    if (hh == 1)
        red[tid & 255] = make_float4(a1r, a1i, a2r, a2i);
    __syncthreads();
    if (hh == 0) {
        float4 o = red[tid];
        a1r += o.x; a1i += o.y; a2r += o.z; a2i += o.w;
        size_t ob = (size_t)blockIdx.x * 512;
        g_X[ob + s * 16 + kw]        = make_float2(a1r, a1i);
        g_X[ob + (16 + s) * 16 + kw] = make_float2(a2r, a2i);
    }
}

// ---------------------------------------------------------------------------
// k3a: time contraction TW[arr][b][row] = sum_t t[b,t] * W[row, t]
// smem-staged coalesced GEMM: 128-row tile, k-chunks of 32, padded stride 36.
// Thread = (2 rows: r, r+64) x (4 batches). Grid: (384, 4), 256 threads.
// ---------------------------------------------------------------------------
__global__ __launch_bounds__(256) void k3a_time(const float* __restrict__ t,
                                                const float* __restrict__ wa,
                                                const float* __restrict__ wb,
                                                const float* __restrict__ wc,
                                                const float* __restrict__ wd) {
    __shared__ float ts[256 * 16];     // [k][b]
    __shared__ float Ws[128 * 36];     // 128 rows x (32 k + 4 pad)
    const int tid = threadIdx.x;

#pragma unroll
    for (int j = tid; j < 4096; j += 256) {
        int b = j & 15, k = j >> 4;
        ts[k * 16 + b] = t[b * 256 + k];
    }

    const float* W = (blockIdx.y == 0) ? wa : (blockIdx.y == 1) ? wb
                   : (blockIdx.y == 2) ? wc : wd;
    float* out = g_TW + (size_t)blockIdx.y * (16 * 49152);

    const int row0 = blockIdx.x * 128;
    const int r  = tid >> 2;      // 0..63
    const int bq = tid & 3;       // batch quad

    float a0[4] = {0, 0, 0, 0}, a1[4] = {0, 0, 0, 0};

#pragma unroll 1
    for (int kc = 0; kc < 8; kc++) {
        __syncthreads();
        // stage 128 rows x 32 k: 1024 float4, 4 per thread, coalesced
#pragma unroll
        for (int j = 0; j < 4; j++) {
            int idx = j * 256 + tid;        // 0..1023
            int rr = idx >> 3, kq = idx & 7;
            float4 v = *(const float4*)(W + (size_t)(row0 + rr) * 256 + kc * 32 + kq * 4);
            *(float4*)&Ws[rr * 36 + kq * 4] = v;
        }
        __syncthreads();

        const float* tsk = ts + (kc * 32) * 16 + bq * 4;
#pragma unroll
        for (int kk = 0; kk < 32; kk++) {
            float w0 = Ws[r * 36 + kk];
            float w1 = Ws[(r + 64) * 36 + kk];
            float4 tv = *(const float4*)(tsk + kk * 16);
            a0[0] += w0 * tv.x; a0[1] += w0 * tv.y;
            a0[2] += w0 * tv.z; a0[3] += w0 * tv.w;
            a1[0] += w1 * tv.x; a1[1] += w1 * tv.y;
            a1[2] += w1 * tv.z; a1[3] += w1 * tv.w;
        }
    }

#pragma unroll
    for (int e = 0; e < 4; e++) {
        out[(size_t)(bq * 4 + e) * 49152 + row0 + r]      = a0[e];
        out[(size_t)(bq * 4 + e) * 49152 + row0 + r + 64] = a1[e];
    }
}

// ---------------------------------------------------------------------------
// k3b: spectral mixing over IC. Grid: 768 x 256.
// ---------------------------------------------------------------------------
__global__ __launch_bounds__(256) void k3b_mix() {
    const int gtid = blockIdx.x * 256 + threadIdx.x;
    const int kw = gtid & 15;
    int r = gtid >> 4;
    const int s = r & 31; r >>= 5;
    const int v = r % 3;  r /= 3;
    const int o = r & 7;
    const int b = r >> 3;

    const int arrbase = (s < 16) ? 0 : 2;
    const int y = s & 15;
    const float* TR = g_TW + (size_t)(arrbase * 16 + b) * 49152;
    const float* TI = g_TW + (size_t)((arrbase + 1) * 16 + b) * 49152;

    float gr = 0.0f, gi = 0.0f;
#pragma unroll
    for (int i = 0; i < 8; i++) {
        float2 xf = g_X[((size_t)((b * 8 + i) * 3 + v) * 32 + s) * 16 + kw];
        int row = (((i * 8 + o) * 3 + v) * 16 + y) * 16 + kw;
        float wr = TR[row], wi = TI[row];
        gr += xf.x * wr - xf.y * wi;
        gi += xf.x * wi + xf.y * wr;
    }
    g_G[gtid] = make_float2(gr, gi);
}

// ---------------------------------------------------------------------------
// k4: inverse DFT over h. Grid 768: block = (group = bx>>1, kw-half = bx&1).
// Thread (h = tid&127, p = tid>>7): p=0 sums even slots (A), p=1 odd (B),
// each over 8 kw. smem exchange combines: Z[h]=A+B, Z[h+128]=A-B.
// Phasor: step e^{2ih}, conj jump at the kh->negative boundary per branch.
// ---------------------------------------------------------------------------
__global__ __launch_bounds__(256) void k4_inv_h() {
    __shared__ float2 Gs[32][8];
    __shared__ float2 Ex[256][8];
    const int tid = threadIdx.x;
    const int group = blockIdx.x >> 1;
    const int khalf = blockIdx.x & 1;

    {
        int sl = tid >> 3, j = tid & 7;
        Gs[sl][j] = g_G[(size_t)group * 512 + sl * 16 + khalf * 8 + j];
    }
    __syncthreads();

    const int h = tid & 127;
    const int p = tid >> 7;

    float s1, c1;
    sincospif((float)h * (1.0f / 128.0f), &s1, &c1);   // e^{+2pi i h/256}
    const float stc = c1 * c1 - s1 * s1;               // e^{+2pi i 2h/256}
    const float sts = 2.0f * c1 * s1;

    float pc, ps;
    if (p == 0) { pc = 1.0f; ps = 0.0f; }
    else        { pc = c1;   ps = s1;   }

    float PR[8], PI[8];
#pragma unroll
    for (int q = 0; q < 8; q++) { PR[q] = 0.0f; PI[q] = 0.0f; }

#pragma unroll 1
    for (int it = 0; it < 16; it++) {
        int sl = it * 2 + p;
        const float2* gp = &Gs[sl][0];
#pragma unroll
        for (int q = 0; q < 8; q++) {
            float2 g = gp[q];
            PR[q] += g.x * pc - g.y * ps;
            PI[q] += g.x * ps + g.y * pc;
        }
        if (it == 7) {
            if (p == 0) {   // step then conj: e^{14ih} -> e^{16ih} -> e^{-16ih}
                float n = pc * stc - ps * sts;
                ps = pc * sts + ps * stc; pc = n;
                ps = -ps;
            } else {        // conj only: e^{15ih} -> e^{-15ih}
                ps = -ps;
            }
        } else {
            float n = pc * stc - ps * sts;
            ps = pc * sts + ps * stc; pc = n;
        }
    }

#pragma unroll
    for (int q = 0; q < 8; q++)
        Ex[tid][q] = make_float2(PR[q], PI[q]);
    __syncthreads();

    const int partner = (p == 0) ? (tid + 128) : (tid - 128);
    float2* zp = g_Z + (size_t)group * 4096 + (h + p * 128) * 16 + khalf * 8;
#pragma unroll
    for (int q = 0; q < 8; q++) {
        float2 other = Ex[partner][q];
        if (p == 0) zp[q] = make_float2(PR[q] + other.x, PI[q] + other.y);
        else        zp[q] = make_float2(other.x - PR[q], other.y - PI[q]);
    }
}

// ---------------------------------------------------------------------------
// k5: inverse real DFT over w, parity split. Tables staged from global.
// Block: 32 rows, 256 threads. Grid: 3072.
// ---------------------------------------------------------------------------
__global__ __launch_bounds__(256) void k5_inv_w(float* __restrict__ out) {
    __shared__ float Ct[16 * 128];
    __shared__ float St[16 * 128];
    __shared__ float2 Zs[512];
    const int tid = threadIdx.x;

    {
        float4* c4 = (float4*)Ct; const float4* gc = (const float4*)g_T5c;
        float4* s4 = (float4*)St; const float4* gs = (const float4*)g_T5s;
#pragma unroll
        for (int j = 0; j < 2; j++) {
            c4[j * 256 + tid] = gc[j * 256 + tid];
            s4[j * 256 + tid] = gs[j * 256 + tid];
        }
    }
    ((float4*)Zs)[tid] = ((const float4*)(g_Z + (size_t)blockIdx.x * 512))[tid];
    __syncthreads();

    const int r  = tid >> 3;
    const int wb = tid & 7;

    float A[16], B[16];
#pragma unroll
    for (int u = 0; u < 16; u++) { A[u] = 0.0f; B[u] = 0.0f; }

#pragma unroll
    for (int kwv = 0; kwv < 16; kwv++) {
        float2 z = Zs[r * 16 + kwv];
#pragma unroll
        for (int u4 = 0; u4 < 4; u4++) {
            float4 c4 = *(const float4*)&Ct[kwv * 128 + wb * 16 + u4 * 4];
            float4 s4 = *(const float4*)&St[kwv * 128 + wb * 16 + u4 * 4];
            float* T = ((kwv & 1) == 0) ? A : B;
            T[u4 * 4 + 0] += z.x * c4.x - z.y * s4.x;
            T[u4 * 4 + 1] += z.x * c4.y - z.y * s4.y;
            T[u4 * 4 + 2] += z.x * c4.z - z.y * s4.z;
            T[u4 * 4 + 3] += z.x * c4.w - z.y * s4.w;
        }
    }

    float* orow = out + (size_t)blockIdx.x * (32 * 256) + r * 256 + wb * 16;
#pragma unroll
    for (int u4 = 0; u4 < 4; u4++) {
        float4 lo = make_float4(A[u4*4+0] + B[u4*4+0], A[u4*4+1] + B[u4*4+1],
                                A[u4*4+2] + B[u4*4+2], A[u4*4+3] + B[u4*4+3]);
        float4 hi = make_float4(A[u4*4+0] - B[u4*4+0], A[u4*4+1] - B[u4*4+1],
                                A[u4*4+2] - B[u4*4+2], A[u4*4+3] - B[u4*4+3]);
        *(float4*)&orow[u4 * 4]       = lo;
        *(float4*)&orow[128 + u4 * 4] = hi;
    }
}

// ---------------------------------------------------------------------------
extern "C" void kernel_launch(void* const* d_in, const int* in_sizes, int n_in,
                              void* d_out, int out_size) {
    const float* t = nullptr;
    const float* x = nullptr;
    const float* w[4] = {nullptr, nullptr, nullptr, nullptr};
    int wn = 0;
    for (int i = 0; i < n_in; i++) {
        if (in_sizes[i] == BB * TD)                      t = (const float*)d_in[i];
        else if (in_sizes[i] == BB * IC * NV * HH * WW)  x = (const float*)d_in[i];
        else if (wn < 4)                                 w[wn++] = (const float*)d_in[i];
    }
    float* out = (float*)d_out;

    k0_tables<<<16, 256>>>();
    k1_fwd_w<<<6144, 128>>>(x);
    k2_fwd_h<<<384, 512>>>();
    k3a_time<<<dim3(384, 4), 256>>>(t, w[0], w[1], w[2], w[3]);
    k3b_mix<<<768, 256>>>();
    k4_inv_h<<<768, 256>>>();
    k5_inv_w<<<3072, 256>>>(out);
}